// round 1
// baseline (speedup 1.0000x reference)
#include <cuda_runtime.h>
#include <math.h>
#include <stdint.h>

#define TSEQ   2048
#define BATCH  2
#define CDIM   1024
#define NHEAD  16
#define HD     64
#define WIN    256
#define MROWS  (BATCH*TSEQ)   /* 4096 */

// Scratch (allocation-free rule: __device__ globals)
static __device__ float g_q[(size_t)MROWS*CDIM];
static __device__ float g_k[(size_t)MROWS*CDIM];
static __device__ float g_v[(size_t)MROWS*CDIM];
static __device__ float g_y[(size_t)MROWS*CDIM];

// ---------------------------------------------------------------------------
// GEMM: Y[M,N] = X[M,K] @ W[K,N] + bias[N]   (all row-major fp32)
// 128x128x16 tile, 256 threads, 8x8 register microtile.
// ---------------------------------------------------------------------------
#define GBM 128
#define GBN 128
#define GBK 16
#define GSTR 132

__global__ __launch_bounds__(256, 2)
void gemm_bias_kernel(const float* __restrict__ X, const float* __restrict__ W,
                      const float* __restrict__ bias, float* __restrict__ Y,
                      int M, int N, int K)
{
    __shared__ __align__(16) float xs[GBK][GSTR];
    __shared__ __align__(16) float ws[GBK][GSTR];
    const int tx = threadIdx.x, ty = threadIdx.y;
    const int tid = ty * 16 + tx;
    const int m0 = blockIdx.y * GBM;
    const int n0 = blockIdx.x * GBN;

    float acc[8][8];
#pragma unroll
    for (int i = 0; i < 8; i++)
#pragma unroll
        for (int j = 0; j < 8; j++) acc[i][j] = 0.f;

    const int xk  = tid & 15;   // k within tile
    const int xr0 = tid >> 4;   // row 0..15
    const int wc  = tid & 127;  // col 0..127
    const int wk0 = tid >> 7;   // k 0..1

    for (int k0 = 0; k0 < K; k0 += GBK) {
#pragma unroll
        for (int rr = 0; rr < 8; rr++)
            xs[xk][xr0 + 16 * rr] = X[(size_t)(m0 + xr0 + 16 * rr) * K + k0 + xk];
#pragma unroll
        for (int kq = 0; kq < 8; kq++)
            ws[wk0 + 2 * kq][wc] = W[(size_t)(k0 + wk0 + 2 * kq) * N + n0 + wc];
        __syncthreads();

#pragma unroll 4
        for (int kk = 0; kk < GBK; kk++) {
            float a[8], b[8];
            float4 a0 = *(const float4*)&xs[kk][ty * 8];
            float4 a1 = *(const float4*)&xs[kk][ty * 8 + 4];
            float4 b0 = *(const float4*)&ws[kk][tx * 8];
            float4 b1 = *(const float4*)&ws[kk][tx * 8 + 4];
            a[0]=a0.x; a[1]=a0.y; a[2]=a0.z; a[3]=a0.w;
            a[4]=a1.x; a[5]=a1.y; a[6]=a1.z; a[7]=a1.w;
            b[0]=b0.x; b[1]=b0.y; b[2]=b0.z; b[3]=b0.w;
            b[4]=b1.x; b[5]=b1.y; b[6]=b1.z; b[7]=b1.w;
#pragma unroll
            for (int i = 0; i < 8; i++)
#pragma unroll
                for (int j = 0; j < 8; j++)
                    acc[i][j] = fmaf(a[i], b[j], acc[i][j]);
        }
        __syncthreads();
    }

    const int cbase = n0 + tx * 8;
    const float4 bi0 = *(const float4*)&bias[cbase];
    const float4 bi1 = *(const float4*)&bias[cbase + 4];
#pragma unroll
    for (int i = 0; i < 8; i++) {
        const size_t r = (size_t)(m0 + ty * 8 + i);
        float4 o0, o1;
        o0.x = acc[i][0] + bi0.x; o0.y = acc[i][1] + bi0.y;
        o0.z = acc[i][2] + bi0.z; o0.w = acc[i][3] + bi0.w;
        o1.x = acc[i][4] + bi1.x; o1.y = acc[i][5] + bi1.y;
        o1.z = acc[i][6] + bi1.z; o1.w = acc[i][7] + bi1.w;
        *(float4*)&Y[r * N + cbase]     = o0;
        *(float4*)&Y[r * N + cbase + 4] = o1;
    }
}

// ---------------------------------------------------------------------------
// Sliding-window flash attention.
// Grid: (T/64, H, B); 256 threads (16x16); O in registers 4x4/thread.
// Q/K/V stored [B,T,H*D] (direct GEMM output) -> row of one head = 64
// contiguous floats at offset (b*T+t)*C + h*64.
// Per query tile [q0, q0+64): key tiles kt in [max(0,qt-4), qt].
// ---------------------------------------------------------------------------
#define SPAD 68

__global__ __launch_bounds__(256)
void attn_kernel(const float* __restrict__ qg, const float* __restrict__ kg,
                 const float* __restrict__ vg, float* __restrict__ yg)
{
    extern __shared__ __align__(16) float dsm[];
    float* qs = dsm;                 // [64][SPAD]
    float* ks = dsm + 64 * SPAD;     // shared K then V
    float* ss = dsm + 2 * 64 * SPAD; // scores / probs
    __shared__ float mrow[64], lrow[64], arow[64];

    const int tx = threadIdx.x, ty = threadIdx.y;
    const int tid = ty * 16 + tx;
    const int qt = blockIdx.x;
    const int h  = blockIdx.y;
    const int b  = blockIdx.z;
    const int q0 = qt * 64;
    const size_t base = ((size_t)b * TSEQ) * CDIM + (size_t)h * HD;

    for (int e = tid; e < 64 * 64; e += 256) {
        int r = e >> 6, d = e & 63;
        qs[r * SPAD + d] = qg[base + (size_t)(q0 + r) * CDIM + d];
    }
    if (tid < 64) { mrow[tid] = -INFINITY; lrow[tid] = 0.f; }
    float o[4][4];
#pragma unroll
    for (int i = 0; i < 4; i++)
#pragma unroll
        for (int j = 0; j < 4; j++) o[i][j] = 0.f;
    __syncthreads();

    const int kt_lo = (qt >= 4) ? (qt - 4) : 0;
    for (int kt = kt_lo; kt <= qt; kt++) {
        const int k0 = kt * 64;
        // load K tile
        for (int e = tid; e < 64 * 64; e += 256) {
            int r = e >> 6, d = e & 63;
            ks[r * SPAD + d] = kg[base + (size_t)(k0 + r) * CDIM + d];
        }
        __syncthreads();

        // S = Q K^T (4x4 microtile per thread)
        float sc[4][4];
#pragma unroll
        for (int i = 0; i < 4; i++)
#pragma unroll
            for (int j = 0; j < 4; j++) sc[i][j] = 0.f;
#pragma unroll 8
        for (int d = 0; d < 64; d++) {
            float a[4], bb[4];
#pragma unroll
            for (int i = 0; i < 4; i++) a[i]  = qs[(ty + 16 * i) * SPAD + d];
#pragma unroll
            for (int j = 0; j < 4; j++) bb[j] = ks[(tx + 16 * j) * SPAD + d];
#pragma unroll
            for (int i = 0; i < 4; i++)
#pragma unroll
                for (int j = 0; j < 4; j++)
                    sc[i][j] = fmaf(a[i], bb[j], sc[i][j]);
        }
        // mask + scale, write to ss
#pragma unroll
        for (int i = 0; i < 4; i++) {
            const int gi = q0 + ty + 16 * i;
#pragma unroll
            for (int j = 0; j < 4; j++) {
                const int gj = k0 + tx + 16 * j;
                const bool valid = (gj <= gi) && (gi - gj <= WIN);
                ss[(ty + 16 * i) * SPAD + tx + 16 * j] =
                    valid ? sc[i][j] * 0.125f : -INFINITY;
            }
        }
        __syncthreads();

        // online softmax: 4 threads per row, 16 cols each.
        {
            const int row = tid >> 2, seg = tid & 3;
            float* srow = ss + row * SPAD + seg * 16;
            float mloc = -INFINITY;
#pragma unroll
            for (int c = 0; c < 16; c++) mloc = fmaxf(mloc, srow[c]);
            mloc = fmaxf(mloc, __shfl_xor_sync(0xffffffffu, mloc, 1));
            mloc = fmaxf(mloc, __shfl_xor_sync(0xffffffffu, mloc, 2));
            const float mold = mrow[row];
            const float mnew = fmaxf(mold, mloc);
            const float al   = __expf(mold - mnew);
            float suml = 0.f;
#pragma unroll
            for (int c = 0; c < 16; c++) {
                float p = __expf(srow[c] - mnew);
                srow[c] = p;
                suml += p;
            }
            suml += __shfl_xor_sync(0xffffffffu, suml, 1);
            suml += __shfl_xor_sync(0xffffffffu, suml, 2);
            if (seg == 0) {
                mrow[row] = mnew;
                lrow[row] = lrow[row] * al + suml;
                arow[row] = al;
            }
        }
        // load V tile into ks (K reads finished before previous sync)
        for (int e = tid; e < 64 * 64; e += 256) {
            int r = e >> 6, d = e & 63;
            ks[r * SPAD + d] = vg[base + (size_t)(k0 + r) * CDIM + d];
        }
        __syncthreads();

        // rescale O, then O += P @ V
#pragma unroll
        for (int i = 0; i < 4; i++) {
            const float al = arow[ty + 16 * i];
#pragma unroll
            for (int j = 0; j < 4; j++) o[i][j] *= al;
        }
#pragma unroll 8
        for (int kk = 0; kk < 64; kk++) {
            float p[4], vv[4];
#pragma unroll
            for (int i = 0; i < 4; i++) p[i]  = ss[(ty + 16 * i) * SPAD + kk];
#pragma unroll
            for (int j = 0; j < 4; j++) vv[j] = ks[kk * SPAD + tx + 16 * j];
#pragma unroll
            for (int i = 0; i < 4; i++)
#pragma unroll
                for (int j = 0; j < 4; j++)
                    o[i][j] = fmaf(p[i], vv[j], o[i][j]);
        }
        __syncthreads();
    }

    // epilogue: normalize and write y in [B,T,H*D]
#pragma unroll
    for (int i = 0; i < 4; i++) {
        const int r = ty + 16 * i;
        const float inv = 1.0f / lrow[r];
#pragma unroll
        for (int j = 0; j < 4; j++) {
            yg[base + (size_t)(q0 + r) * CDIM + tx + 16 * j] = o[i][j] * inv;
        }
    }
}

// ---------------------------------------------------------------------------
extern "C" void kernel_launch(void* const* d_in, const int* in_sizes, int n_in,
                              void* d_out, int out_size)
{
    const float* x  = (const float*)d_in[0];
    const float* Wq = (const float*)d_in[1];
    const float* bq = (const float*)d_in[2];
    const float* Wk = (const float*)d_in[3];
    const float* bk = (const float*)d_in[4];
    const float* Wv = (const float*)d_in[5];
    const float* bv = (const float*)d_in[6];
    const float* Wo = (const float*)d_in[7];
    const float* bo = (const float*)d_in[8];
    float* out = (float*)d_out;
    (void)in_sizes; (void)n_in; (void)out_size;

    float *qp, *kp, *vp, *yp;
    cudaGetSymbolAddress((void**)&qp, g_q);
    cudaGetSymbolAddress((void**)&kp, g_k);
    cudaGetSymbolAddress((void**)&vp, g_v);
    cudaGetSymbolAddress((void**)&yp, g_y);

    const int ATT_SMEM = 3 * 64 * SPAD * (int)sizeof(float);
    cudaFuncSetAttribute(attn_kernel,
                         cudaFuncAttributeMaxDynamicSharedMemorySize, ATT_SMEM);

    dim3 blk(16, 16);
    dim3 ggrid(CDIM / GBN, MROWS / GBM);

    gemm_bias_kernel<<<ggrid, blk>>>(x, Wq, bq, qp, MROWS, CDIM, CDIM);
    gemm_bias_kernel<<<ggrid, blk>>>(x, Wk, bk, kp, MROWS, CDIM, CDIM);
    gemm_bias_kernel<<<ggrid, blk>>>(x, Wv, bv, vp, MROWS, CDIM, CDIM);

    attn_kernel<<<dim3(TSEQ / 64, NHEAD, BATCH), blk, ATT_SMEM>>>(qp, kp, vp, yp);

    gemm_bias_kernel<<<ggrid, blk>>>(yp, Wo, bo, out, MROWS, CDIM, CDIM);
}

// round 4
// speedup vs baseline: 1.9774x; 1.9774x over previous
#include <cuda_runtime.h>
#include <math.h>
#include <stdint.h>

#define TSEQ   2048
#define BATCH  2
#define CDIM   1024
#define NHEAD  16
#define HD     64
#define WIN    256
#define MROWS  (BATCH*TSEQ)   /* 4096 */

// Scratch (allocation-free rule: __device__ globals)
static __device__ float g_q[(size_t)MROWS*CDIM];
static __device__ float g_k[(size_t)MROWS*CDIM];
static __device__ float g_v[(size_t)MROWS*CDIM];
static __device__ float g_y[(size_t)MROWS*CDIM];

// ===========================================================================
// tf32 mma.sync GEMM: Y[M,N] = X[M,K] @ W[K,N] + bias
// CTA 128x128, BK=16, 8 warps (2 M x 4 N), warp tile 64x32,
// mma.m16n8k8.tf32 (b32 operands), cp.async double buffering.
// ===========================================================================
#define BM 128
#define BN 128
#define BK 16
#define ASTR 20    /* floats per A smem row (16 + pad) */
#define BSTR 132   /* floats per B smem row (128 + pad) */

__device__ __forceinline__ uint32_t smem_u32(const void* p) {
    uint32_t a;
    asm("{ .reg .u64 t; cvta.to.shared.u64 t, %1; cvt.u32.u64 %0, t; }" : "=r"(a) : "l"(p));
    return a;
}
__device__ __forceinline__ void cp_async16(uint32_t s, const void* g) {
    asm volatile("cp.async.cg.shared.global [%0], [%1], 16;" :: "r"(s), "l"(g) : "memory");
}
__device__ __forceinline__ void cp_commit() {
    asm volatile("cp.async.commit_group;" ::: "memory");
}
template <int N_>
__device__ __forceinline__ void cp_wait() {
    asm volatile("cp.async.wait_group %0;" :: "n"(N_) : "memory");
}
__device__ __forceinline__ uint32_t to_tf32_bits(float x) {
    uint32_t y;
    asm("cvt.rna.tf32.f32 %0, %1;" : "=r"(y) : "f"(x));
    return y;
}
__device__ __forceinline__ void mma_tf32(float* c, const uint32_t* a, const uint32_t* b) {
    asm volatile(
        "mma.sync.aligned.m16n8k8.row.col.f32.tf32.tf32.f32 "
        "{%0,%1,%2,%3}, {%4,%5,%6,%7}, {%8,%9}, {%0,%1,%2,%3};"
        : "+f"(c[0]), "+f"(c[1]), "+f"(c[2]), "+f"(c[3])
        : "r"(a[0]), "r"(a[1]), "r"(a[2]), "r"(a[3]), "r"(b[0]), "r"(b[1]));
}

__global__ __launch_bounds__(256, 2)
void gemm_mma_kernel(const float* __restrict__ X, const float* __restrict__ W,
                     const float* __restrict__ bias, float* __restrict__ Y,
                     int M, int N, int K)
{
    __shared__ __align__(16) float As[2][BM * ASTR];
    __shared__ __align__(16) float Bs[2][BK * BSTR];

    const int tid  = threadIdx.x;
    const int wid  = tid >> 5;
    const int lane = tid & 31;
    const int wm   = wid & 1;        // 0..1
    const int wn   = wid >> 1;       // 0..3
    const int m0 = blockIdx.y * BM;
    const int n0 = blockIdx.x * BN;
    const int grp = lane >> 2;       // 0..7
    const int qid = lane & 3;        // 0..3

    float c[4][4][4];
#pragma unroll
    for (int i = 0; i < 4; i++)
#pragma unroll
        for (int j = 0; j < 4; j++)
#pragma unroll
            for (int r = 0; r < 4; r++) c[i][j][r] = 0.f;

    const int a_i0 = tid * 2, a_i1 = tid * 2 + 1;
    const int am[2] = { a_i0 >> 2, a_i1 >> 2 };
    const int as[2] = { a_i0 & 3,  a_i1 & 3 };
    const int bk_[2] = { a_i0 >> 5, a_i1 >> 5 };
    const int bs_[2] = { a_i0 & 31, a_i1 & 31 };

    const uint32_t sA[2] = { smem_u32(As[0]), smem_u32(As[1]) };
    const uint32_t sB[2] = { smem_u32(Bs[0]), smem_u32(Bs[1]) };

#define LOAD_STAGE(st, k0)                                                        \
    do {                                                                          \
        _Pragma("unroll")                                                         \
        for (int q = 0; q < 2; q++)                                               \
            cp_async16(sA[st] + (uint32_t)(am[q] * ASTR + as[q] * 4) * 4,         \
                       &X[(size_t)(m0 + am[q]) * K + (k0) + as[q] * 4]);          \
        _Pragma("unroll")                                                         \
        for (int q = 0; q < 2; q++)                                               \
            cp_async16(sB[st] + (uint32_t)(bk_[q] * BSTR + bs_[q] * 4) * 4,       \
                       &W[(size_t)((k0) + bk_[q]) * N + n0 + bs_[q] * 4]);        \
        cp_commit();                                                              \
    } while (0)

    LOAD_STAGE(0, 0);

    const int NIT = K / BK;   // 64
    for (int kt = 0; kt < NIT; kt++) {
        const int st = kt & 1;
        if (kt + 1 < NIT) {
            LOAD_STAGE(st ^ 1, (kt + 1) * BK);
            cp_wait<1>();
        } else {
            cp_wait<0>();
        }
        __syncthreads();

        const float* Ab = As[st];
        const float* Bb = Bs[st];
#pragma unroll
        for (int kk = 0; kk < 2; kk++) {
            const int kof = kk * 8;
            uint32_t af[4][4];
#pragma unroll
            for (int i = 0; i < 4; i++) {
                const int row = wm * 64 + i * 16 + grp;
                const int col = kof + qid;
                af[i][0] = to_tf32_bits(Ab[row * ASTR + col]);
                af[i][1] = to_tf32_bits(Ab[(row + 8) * ASTR + col]);
                af[i][2] = to_tf32_bits(Ab[row * ASTR + col + 4]);
                af[i][3] = to_tf32_bits(Ab[(row + 8) * ASTR + col + 4]);
            }
            uint32_t bf[4][2];
#pragma unroll
            for (int j = 0; j < 4; j++) {
                const int col = wn * 32 + j * 8 + grp;
                bf[j][0] = to_tf32_bits(Bb[(kof + qid) * BSTR + col]);
                bf[j][1] = to_tf32_bits(Bb[(kof + qid + 4) * BSTR + col]);
            }
#pragma unroll
            for (int i = 0; i < 4; i++)
#pragma unroll
                for (int j = 0; j < 4; j++)
                    mma_tf32(c[i][j], af[i], bf[j]);
        }
        __syncthreads();
    }

    // epilogue
#pragma unroll
    for (int i = 0; i < 4; i++) {
        const int row = m0 + wm * 64 + i * 16 + grp;
#pragma unroll
        for (int j = 0; j < 4; j++) {
            const int col = n0 + wn * 32 + j * 8 + 2 * qid;
            const float b0 = bias[col], b1 = bias[col + 1];
            float2 v0 = { c[i][j][0] + b0, c[i][j][1] + b1 };
            float2 v1 = { c[i][j][2] + b0, c[i][j][3] + b1 };
            *(float2*)&Y[(size_t)row * N + col]       = v0;
            *(float2*)&Y[(size_t)(row + 8) * N + col] = v1;
        }
    }
#undef LOAD_STAGE
}

// ---------------------------------------------------------------------------
// Sliding-window flash attention (unchanged).
// ---------------------------------------------------------------------------
#define SPAD 68

__global__ __launch_bounds__(256)
void attn_kernel(const float* __restrict__ qg, const float* __restrict__ kg,
                 const float* __restrict__ vg, float* __restrict__ yg)
{
    extern __shared__ __align__(16) float dsm[];
    float* qs = dsm;
    float* ks = dsm + 64 * SPAD;
    float* ss = dsm + 2 * 64 * SPAD;
    __shared__ float mrow[64], lrow[64], arow[64];

    const int tx = threadIdx.x, ty = threadIdx.y;
    const int tid = ty * 16 + tx;
    const int qt = blockIdx.x;
    const int h  = blockIdx.y;
    const int b  = blockIdx.z;
    const int q0 = qt * 64;
    const size_t base = ((size_t)b * TSEQ) * CDIM + (size_t)h * HD;

    for (int e = tid; e < 64 * 64; e += 256) {
        int r = e >> 6, d = e & 63;
        qs[r * SPAD + d] = qg[base + (size_t)(q0 + r) * CDIM + d];
    }
    if (tid < 64) { mrow[tid] = -INFINITY; lrow[tid] = 0.f; }
    float o[4][4];
#pragma unroll
    for (int i = 0; i < 4; i++)
#pragma unroll
        for (int j = 0; j < 4; j++) o[i][j] = 0.f;
    __syncthreads();

    const int kt_lo = (qt >= 4) ? (qt - 4) : 0;
    for (int kt = kt_lo; kt <= qt; kt++) {
        const int k0 = kt * 64;
        for (int e = tid; e < 64 * 64; e += 256) {
            int r = e >> 6, d = e & 63;
            ks[r * SPAD + d] = kg[base + (size_t)(k0 + r) * CDIM + d];
        }
        __syncthreads();

        float sc[4][4];
#pragma unroll
        for (int i = 0; i < 4; i++)
#pragma unroll
            for (int j = 0; j < 4; j++) sc[i][j] = 0.f;
#pragma unroll 8
        for (int d = 0; d < 64; d++) {
            float a[4], bb[4];
#pragma unroll
            for (int i = 0; i < 4; i++) a[i]  = qs[(ty + 16 * i) * SPAD + d];
#pragma unroll
            for (int j = 0; j < 4; j++) bb[j] = ks[(tx + 16 * j) * SPAD + d];
#pragma unroll
            for (int i = 0; i < 4; i++)
#pragma unroll
                for (int j = 0; j < 4; j++)
                    sc[i][j] = fmaf(a[i], bb[j], sc[i][j]);
        }
#pragma unroll
        for (int i = 0; i < 4; i++) {
            const int gi = q0 + ty + 16 * i;
#pragma unroll
            for (int j = 0; j < 4; j++) {
                const int gj = k0 + tx + 16 * j;
                const bool valid = (gj <= gi) && (gi - gj <= WIN);
                ss[(ty + 16 * i) * SPAD + tx + 16 * j] =
                    valid ? sc[i][j] * 0.125f : -INFINITY;
            }
        }
        __syncthreads();

        {
            const int row = tid >> 2, seg = tid & 3;
            float* srow = ss + row * SPAD + seg * 16;
            float mloc = -INFINITY;
#pragma unroll
            for (int c2 = 0; c2 < 16; c2++) mloc = fmaxf(mloc, srow[c2]);
            mloc = fmaxf(mloc, __shfl_xor_sync(0xffffffffu, mloc, 1));
            mloc = fmaxf(mloc, __shfl_xor_sync(0xffffffffu, mloc, 2));
            const float mold = mrow[row];
            const float mnew = fmaxf(mold, mloc);
            const float al   = __expf(mold - mnew);
            float suml = 0.f;
#pragma unroll
            for (int c2 = 0; c2 < 16; c2++) {
                float p = __expf(srow[c2] - mnew);
                srow[c2] = p;
                suml += p;
            }
            suml += __shfl_xor_sync(0xffffffffu, suml, 1);
            suml += __shfl_xor_sync(0xffffffffu, suml, 2);
            if (seg == 0) {
                mrow[row] = mnew;
                lrow[row] = lrow[row] * al + suml;
                arow[row] = al;
            }
        }
        for (int e = tid; e < 64 * 64; e += 256) {
            int r = e >> 6, d = e & 63;
            ks[r * SPAD + d] = vg[base + (size_t)(k0 + r) * CDIM + d];
        }
        __syncthreads();

#pragma unroll
        for (int i = 0; i < 4; i++) {
            const float al = arow[ty + 16 * i];
#pragma unroll
            for (int j = 0; j < 4; j++) o[i][j] *= al;
        }
#pragma unroll 8
        for (int kk = 0; kk < 64; kk++) {
            float p[4], vv[4];
#pragma unroll
            for (int i = 0; i < 4; i++) p[i]  = ss[(ty + 16 * i) * SPAD + kk];
#pragma unroll
            for (int j = 0; j < 4; j++) vv[j] = ks[kk * SPAD + tx + 16 * j];
#pragma unroll
            for (int i = 0; i < 4; i++)
#pragma unroll
                for (int j = 0; j < 4; j++)
                    o[i][j] = fmaf(p[i], vv[j], o[i][j]);
        }
        __syncthreads();
    }

#pragma unroll
    for (int i = 0; i < 4; i++) {
        const int r = ty + 16 * i;
        const float inv = 1.0f / lrow[r];
#pragma unroll
        for (int j = 0; j < 4; j++) {
            yg[base + (size_t)(q0 + r) * CDIM + tx + 16 * j] = o[i][j] * inv;
        }
    }
}

// ---------------------------------------------------------------------------
extern "C" void kernel_launch(void* const* d_in, const int* in_sizes, int n_in,
                              void* d_out, int out_size)
{
    const float* x  = (const float*)d_in[0];
    const float* Wq = (const float*)d_in[1];
    const float* bq = (const float*)d_in[2];
    const float* Wk = (const float*)d_in[3];
    const float* bk = (const float*)d_in[4];
    const float* Wv = (const float*)d_in[5];
    const float* bv = (const float*)d_in[6];
    const float* Wo = (const float*)d_in[7];
    const float* bo = (const float*)d_in[8];
    float* out = (float*)d_out;
    (void)in_sizes; (void)n_in; (void)out_size;

    float *qp, *kp, *vp, *yp;
    cudaGetSymbolAddress((void**)&qp, g_q);
    cudaGetSymbolAddress((void**)&kp, g_k);
    cudaGetSymbolAddress((void**)&vp, g_v);
    cudaGetSymbolAddress((void**)&yp, g_y);

    const int ATT_SMEM = 3 * 64 * SPAD * (int)sizeof(float);
    cudaFuncSetAttribute(attn_kernel,
                         cudaFuncAttributeMaxDynamicSharedMemorySize, ATT_SMEM);

    dim3 ggrid(CDIM / BN, MROWS / BM);
    gemm_mma_kernel<<<ggrid, 256>>>(x, Wq, bq, qp, MROWS, CDIM, CDIM);
    gemm_mma_kernel<<<ggrid, 256>>>(x, Wk, bk, kp, MROWS, CDIM, CDIM);
    gemm_mma_kernel<<<ggrid, 256>>>(x, Wv, bv, vp, MROWS, CDIM, CDIM);

    attn_kernel<<<dim3(TSEQ / 64, NHEAD, BATCH), dim3(16, 16), ATT_SMEM>>>(qp, kp, vp, yp);

    gemm_mma_kernel<<<ggrid, 256>>>(yp, Wo, bo, out, MROWS, CDIM, CDIM);
}

// round 5
// speedup vs baseline: 2.3859x; 1.2066x over previous
#include <cuda_runtime.h>
#include <math.h>
#include <stdint.h>

#define TSEQ   2048
#define BATCH  2
#define CDIM   1024
#define NHEAD  16
#define HD     64
#define WIN    256
#define MROWS  (BATCH*TSEQ)   /* 4096 */

// Scratch (allocation-free rule: __device__ globals)
static __device__ float g_q[(size_t)MROWS*CDIM];
static __device__ float g_k[(size_t)MROWS*CDIM];
static __device__ float g_v[(size_t)MROWS*CDIM];
static __device__ float g_y[(size_t)MROWS*CDIM];

// ===========================================================================
// Common PTX helpers
// ===========================================================================
__device__ __forceinline__ uint32_t smem_u32(const void* p) {
    uint32_t a;
    asm("{ .reg .u64 t; cvta.to.shared.u64 t, %1; cvt.u32.u64 %0, t; }" : "=r"(a) : "l"(p));
    return a;
}
__device__ __forceinline__ void cp_async16(uint32_t s, const void* g) {
    asm volatile("cp.async.cg.shared.global [%0], [%1], 16;" :: "r"(s), "l"(g) : "memory");
}
__device__ __forceinline__ void cp_commit() {
    asm volatile("cp.async.commit_group;" ::: "memory");
}
template <int N_>
__device__ __forceinline__ void cp_wait() {
    asm volatile("cp.async.wait_group %0;" :: "n"(N_) : "memory");
}
__device__ __forceinline__ uint32_t to_tf32_bits(float x) {
    uint32_t y;
    asm("cvt.rna.tf32.f32 %0, %1;" : "=r"(y) : "f"(x));
    return y;
}
__device__ __forceinline__ float to_tf32f(float x) {
    return __uint_as_float(to_tf32_bits(x));
}
__device__ __forceinline__ void mma_tf32(float* c, const uint32_t* a, const uint32_t* b) {
    asm volatile(
        "mma.sync.aligned.m16n8k8.row.col.f32.tf32.tf32.f32 "
        "{%0,%1,%2,%3}, {%4,%5,%6,%7}, {%8,%9}, {%0,%1,%2,%3};"
        : "+f"(c[0]), "+f"(c[1]), "+f"(c[2]), "+f"(c[3])
        : "r"(a[0]), "r"(a[1]), "r"(a[2]), "r"(a[3]), "r"(b[0]), "r"(b[1]));
}

// ===========================================================================
// tf32 mma.sync GEMM: Y[M,N] = X[M,K] @ W[K,N] + bias   (unchanged from R4)
// ===========================================================================
#define BM 128
#define BN 128
#define BK 16
#define ASTR 20
#define BSTR 132

__global__ __launch_bounds__(256, 2)
void gemm_mma_kernel(const float* __restrict__ X, const float* __restrict__ W,
                     const float* __restrict__ bias, float* __restrict__ Y,
                     int M, int N, int K)
{
    __shared__ __align__(16) float As[2][BM * ASTR];
    __shared__ __align__(16) float Bs[2][BK * BSTR];

    const int tid  = threadIdx.x;
    const int wid  = tid >> 5;
    const int lane = tid & 31;
    const int wm   = wid & 1;
    const int wn   = wid >> 1;
    const int m0 = blockIdx.y * BM;
    const int n0 = blockIdx.x * BN;
    const int grp = lane >> 2;
    const int qid = lane & 3;

    float c[4][4][4];
#pragma unroll
    for (int i = 0; i < 4; i++)
#pragma unroll
        for (int j = 0; j < 4; j++)
#pragma unroll
            for (int r = 0; r < 4; r++) c[i][j][r] = 0.f;

    const int a_i0 = tid * 2, a_i1 = tid * 2 + 1;
    const int am[2] = { a_i0 >> 2, a_i1 >> 2 };
    const int as[2] = { a_i0 & 3,  a_i1 & 3 };
    const int bk_[2] = { a_i0 >> 5, a_i1 >> 5 };
    const int bs_[2] = { a_i0 & 31, a_i1 & 31 };

    const uint32_t sA[2] = { smem_u32(As[0]), smem_u32(As[1]) };
    const uint32_t sB[2] = { smem_u32(Bs[0]), smem_u32(Bs[1]) };

#define LOAD_STAGE(st, k0)                                                        \
    do {                                                                          \
        _Pragma("unroll")                                                         \
        for (int q = 0; q < 2; q++)                                               \
            cp_async16(sA[st] + (uint32_t)(am[q] * ASTR + as[q] * 4) * 4,         \
                       &X[(size_t)(m0 + am[q]) * K + (k0) + as[q] * 4]);          \
        _Pragma("unroll")                                                         \
        for (int q = 0; q < 2; q++)                                               \
            cp_async16(sB[st] + (uint32_t)(bk_[q] * BSTR + bs_[q] * 4) * 4,       \
                       &W[(size_t)((k0) + bk_[q]) * N + n0 + bs_[q] * 4]);        \
        cp_commit();                                                              \
    } while (0)

    LOAD_STAGE(0, 0);

    const int NIT = K / BK;
    for (int kt = 0; kt < NIT; kt++) {
        const int st = kt & 1;
        if (kt + 1 < NIT) {
            LOAD_STAGE(st ^ 1, (kt + 1) * BK);
            cp_wait<1>();
        } else {
            cp_wait<0>();
        }
        __syncthreads();

        const float* Ab = As[st];
        const float* Bb = Bs[st];
#pragma unroll
        for (int kk = 0; kk < 2; kk++) {
            const int kof = kk * 8;
            uint32_t af[4][4];
#pragma unroll
            for (int i = 0; i < 4; i++) {
                const int row = wm * 64 + i * 16 + grp;
                const int col = kof + qid;
                af[i][0] = to_tf32_bits(Ab[row * ASTR + col]);
                af[i][1] = to_tf32_bits(Ab[(row + 8) * ASTR + col]);
                af[i][2] = to_tf32_bits(Ab[row * ASTR + col + 4]);
                af[i][3] = to_tf32_bits(Ab[(row + 8) * ASTR + col + 4]);
            }
            uint32_t bf[4][2];
#pragma unroll
            for (int j = 0; j < 4; j++) {
                const int col = wn * 32 + j * 8 + grp;
                bf[j][0] = to_tf32_bits(Bb[(kof + qid) * BSTR + col]);
                bf[j][1] = to_tf32_bits(Bb[(kof + qid + 4) * BSTR + col]);
            }
#pragma unroll
            for (int i = 0; i < 4; i++)
#pragma unroll
                for (int j = 0; j < 4; j++)
                    mma_tf32(c[i][j], af[i], bf[j]);
        }
        __syncthreads();
    }

#pragma unroll
    for (int i = 0; i < 4; i++) {
        const int row = m0 + wm * 64 + i * 16 + grp;
#pragma unroll
        for (int j = 0; j < 4; j++) {
            const int col = n0 + wn * 32 + j * 8 + 2 * qid;
            const float b0 = bias[col], b1 = bias[col + 1];
            float2 v0 = { c[i][j][0] + b0, c[i][j][1] + b1 };
            float2 v1 = { c[i][j][2] + b0, c[i][j][3] + b1 };
            *(float2*)&Y[(size_t)row * N + col]       = v0;
            *(float2*)&Y[(size_t)(row + 8) * N + col] = v1;
        }
    }
#undef LOAD_STAGE
}

// ---------------------------------------------------------------------------
// Sliding-window flash attention with tf32 mma for QK^T and P.V
// 256 threads = 8 warps; warp w owns m16 rows (w&3)*16, n32 cols (w>>2)*32.
// Q/K/V/P are tf32-rounded when written to smem.
// ---------------------------------------------------------------------------
#define SPAD 68

__global__ __launch_bounds__(256)
void attn_kernel(const float* __restrict__ qg, const float* __restrict__ kg,
                 const float* __restrict__ vg, float* __restrict__ yg)
{
    extern __shared__ __align__(16) float dsm[];
    float* qs = dsm;                 // [64][SPAD] tf32-rounded Q
    float* ks = dsm + 64 * SPAD;     // K then V (tf32-rounded)
    float* ss = dsm + 2 * 64 * SPAD; // scores / probs
    __shared__ float mrow[64], lrow[64], arow[64];

    const int tid  = threadIdx.x;
    const int wid  = tid >> 5;
    const int lane = tid & 31;
    const int grp  = lane >> 2;      // 0..7
    const int qid  = lane & 3;       // 0..3
    const int mrow0 = (wid & 3) * 16;
    const int ncol0 = (wid >> 2) * 32;

    const int qt = blockIdx.x;
    const int h  = blockIdx.y;
    const int b  = blockIdx.z;
    const int q0 = qt * 64;
    const size_t base = ((size_t)b * TSEQ) * CDIM + (size_t)h * HD;

    for (int e = tid; e < 64 * 64; e += 256) {
        int r = e >> 6, d = e & 63;
        qs[r * SPAD + d] = to_tf32f(qg[base + (size_t)(q0 + r) * CDIM + d]);
    }
    if (tid < 64) { mrow[tid] = -INFINITY; lrow[tid] = 0.f; }

    float oacc[4][4];
#pragma unroll
    for (int j = 0; j < 4; j++)
#pragma unroll
        for (int r = 0; r < 4; r++) oacc[j][r] = 0.f;
    __syncthreads();

    const int kt_lo = (qt >= 4) ? (qt - 4) : 0;
    for (int kt = kt_lo; kt <= qt; kt++) {
        const int k0 = kt * 64;
        // load K tile (tf32-rounded)
        for (int e = tid; e < 64 * 64; e += 256) {
            int r = e >> 6, d = e & 63;
            ks[r * SPAD + d] = to_tf32f(kg[base + (size_t)(k0 + r) * CDIM + d]);
        }
        __syncthreads();

        // ---- S = Q K^T via mma: per warp m16 x n32, k=64 ----
        float sacc[4][4];
#pragma unroll
        for (int j = 0; j < 4; j++)
#pragma unroll
            for (int r = 0; r < 4; r++) sacc[j][r] = 0.f;

#pragma unroll
        for (int k8 = 0; k8 < 64; k8 += 8) {
            uint32_t af[4];
            const int ra = mrow0 + grp;
            af[0] = __float_as_uint(qs[ra * SPAD + k8 + qid]);
            af[1] = __float_as_uint(qs[(ra + 8) * SPAD + k8 + qid]);
            af[2] = __float_as_uint(qs[ra * SPAD + k8 + qid + 4]);
            af[3] = __float_as_uint(qs[(ra + 8) * SPAD + k8 + qid + 4]);
#pragma unroll
            for (int j = 0; j < 4; j++) {
                const int cn = ncol0 + j * 8 + grp;
                uint32_t bf[2];
                bf[0] = __float_as_uint(ks[cn * SPAD + k8 + qid]);
                bf[1] = __float_as_uint(ks[cn * SPAD + k8 + qid + 4]);
                mma_tf32(sacc[j], af, bf);
            }
        }

        // mask + scale, write S to smem
#pragma unroll
        for (int j = 0; j < 4; j++) {
            const int col = ncol0 + j * 8 + 2 * qid;
            const int gj0 = k0 + col, gj1 = gj0 + 1;
            const int r0 = mrow0 + grp;
            const int gi0 = q0 + r0, gi1 = gi0 + 8;
            const bool v00 = (gj0 <= gi0) && (gi0 - gj0 <= WIN);
            const bool v01 = (gj1 <= gi0) && (gi0 - gj1 <= WIN);
            const bool v10 = (gj0 <= gi1) && (gi1 - gj0 <= WIN);
            const bool v11 = (gj1 <= gi1) && (gi1 - gj1 <= WIN);
            ss[r0 * SPAD + col]           = v00 ? sacc[j][0] * 0.125f : -INFINITY;
            ss[r0 * SPAD + col + 1]       = v01 ? sacc[j][1] * 0.125f : -INFINITY;
            ss[(r0 + 8) * SPAD + col]     = v10 ? sacc[j][2] * 0.125f : -INFINITY;
            ss[(r0 + 8) * SPAD + col + 1] = v11 ? sacc[j][3] * 0.125f : -INFINITY;
        }
        __syncthreads();

        // ---- online softmax: 4 threads per row, 16 cols each; P tf32-rounded ----
        {
            const int row = tid >> 2, seg = tid & 3;
            float* srow = ss + row * SPAD + seg * 16;
            float mloc = -INFINITY;
#pragma unroll
            for (int c2 = 0; c2 < 16; c2++) mloc = fmaxf(mloc, srow[c2]);
            mloc = fmaxf(mloc, __shfl_xor_sync(0xffffffffu, mloc, 1));
            mloc = fmaxf(mloc, __shfl_xor_sync(0xffffffffu, mloc, 2));
            const float mold = mrow[row];
            const float mnew = fmaxf(mold, mloc);
            const float al   = __expf(mold - mnew);
            float suml = 0.f;
#pragma unroll
            for (int c2 = 0; c2 < 16; c2++) {
                float p = __expf(srow[c2] - mnew);
                suml += p;
                srow[c2] = to_tf32f(p);
            }
            suml += __shfl_xor_sync(0xffffffffu, suml, 1);
            suml += __shfl_xor_sync(0xffffffffu, suml, 2);
            if (seg == 0) {
                mrow[row] = mnew;
                lrow[row] = lrow[row] * al + suml;
                arow[row] = al;
            }
        }
        // load V tile into ks (tf32-rounded)
        for (int e = tid; e < 64 * 64; e += 256) {
            int r = e >> 6, d = e & 63;
            ks[r * SPAD + d] = to_tf32f(vg[base + (size_t)(k0 + r) * CDIM + d]);
        }
        __syncthreads();

        // ---- rescale O, then O += P @ V via mma ----
        {
            const float a_lo = arow[mrow0 + grp];
            const float a_hi = arow[mrow0 + grp + 8];
#pragma unroll
            for (int j = 0; j < 4; j++) {
                oacc[j][0] *= a_lo; oacc[j][1] *= a_lo;
                oacc[j][2] *= a_hi; oacc[j][3] *= a_hi;
            }
        }
#pragma unroll
        for (int k8 = 0; k8 < 64; k8 += 8) {
            uint32_t af[4];
            const int ra = mrow0 + grp;
            af[0] = __float_as_uint(ss[ra * SPAD + k8 + qid]);
            af[1] = __float_as_uint(ss[(ra + 8) * SPAD + k8 + qid]);
            af[2] = __float_as_uint(ss[ra * SPAD + k8 + qid + 4]);
            af[3] = __float_as_uint(ss[(ra + 8) * SPAD + k8 + qid + 4]);
#pragma unroll
            for (int j = 0; j < 4; j++) {
                const int cn = ncol0 + j * 8 + grp;
                uint32_t bf[2];
                bf[0] = __float_as_uint(ks[(k8 + qid) * SPAD + cn]);
                bf[1] = __float_as_uint(ks[(k8 + qid + 4) * SPAD + cn]);
                mma_tf32(oacc[j], af, bf);
            }
        }
        __syncthreads();
    }

    // epilogue: normalize and write y
    {
        const int r0 = mrow0 + grp;
        const float inv_lo = 1.0f / lrow[r0];
        const float inv_hi = 1.0f / lrow[r0 + 8];
#pragma unroll
        for (int j = 0; j < 4; j++) {
            const int col = ncol0 + j * 8 + 2 * qid;
            float2 v0 = { oacc[j][0] * inv_lo, oacc[j][1] * inv_lo };
            float2 v1 = { oacc[j][2] * inv_hi, oacc[j][3] * inv_hi };
            *(float2*)&yg[base + (size_t)(q0 + r0) * CDIM + col]     = v0;
            *(float2*)&yg[base + (size_t)(q0 + r0 + 8) * CDIM + col] = v1;
        }
    }
}

// ---------------------------------------------------------------------------
extern "C" void kernel_launch(void* const* d_in, const int* in_sizes, int n_in,
                              void* d_out, int out_size)
{
    const float* x  = (const float*)d_in[0];
    const float* Wq = (const float*)d_in[1];
    const float* bq = (const float*)d_in[2];
    const float* Wk = (const float*)d_in[3];
    const float* bk = (const float*)d_in[4];
    const float* Wv = (const float*)d_in[5];
    const float* bv = (const float*)d_in[6];
    const float* Wo = (const float*)d_in[7];
    const float* bo = (const float*)d_in[8];
    float* out = (float*)d_out;
    (void)in_sizes; (void)n_in; (void)out_size;

    float *qp, *kp, *vp, *yp;
    cudaGetSymbolAddress((void**)&qp, g_q);
    cudaGetSymbolAddress((void**)&kp, g_k);
    cudaGetSymbolAddress((void**)&vp, g_v);
    cudaGetSymbolAddress((void**)&yp, g_y);

    const int ATT_SMEM = 3 * 64 * SPAD * (int)sizeof(float);
    cudaFuncSetAttribute(attn_kernel,
                         cudaFuncAttributeMaxDynamicSharedMemorySize, ATT_SMEM);

    dim3 ggrid(CDIM / BN, MROWS / BM);
    gemm_mma_kernel<<<ggrid, 256>>>(x, Wq, bq, qp, MROWS, CDIM, CDIM);
    gemm_mma_kernel<<<ggrid, 256>>>(x, Wk, bk, kp, MROWS, CDIM, CDIM);
    gemm_mma_kernel<<<ggrid, 256>>>(x, Wv, bv, vp, MROWS, CDIM, CDIM);

    attn_kernel<<<dim3(TSEQ / 64, NHEAD, BATCH), 256, ATT_SMEM>>>(qp, kp, vp, yp);

    gemm_mma_kernel<<<ggrid, 256>>>(yp, Wo, bo, out, MROWS, CDIM, CDIM);
}